// round 10
// baseline (speedup 1.0000x reference)
#include <cuda_runtime.h>
#include <math_constants.h>
#include <cstdint>
#include <cstddef>

// ---------------- Problem constants ----------------
#define BB 2
#define TT 2048
#define HH 1024
#define VV 50257
#define MTOT (BB*TT)          // 4096
#define NT 393                // ceil(50257/128) N tiles

// ---------------- GEMM tiling ----------------
#define TM 256
#define TN 128
#define NST 8                 // pipeline stages (TK=16 each)
#define NK 64                 // K iterations of 16
#define NTHREADS 256          // 8 warps, each m64n64

#define A_U 8192              // bytes per packed A kt16 unit (128 rows)
#define B_U 8192              // bytes per packed B kt16 unit
#define ST  24576             // stage = 2*A_U (256 rows) + B_U
#define SMEM_TOTAL (NST*ST)   // 196608 dynamic

// ---------------- device scratch ----------------
// A_packed: [mtile 0..31][kt 0..63] tiles of 8KB, fragment order:
//   unit16B v = block(0..7)*64 + slab(0..1)*32 + lane(0..31)
//   regs = A[r0][c0], A[r0+8][c0], A[r0][c0+4], A[r0+8][c0+4]
//   r0 = mtile*128+block*16+(lane>>2), c0 = kt*16+slab*8+(lane&3)
__device__ float A_packed[MTOT*HH];                    // 16 MB
// W_packed: [ntile 0..392][kt 0..63] tiles of 8KB:
//   unit16B v = cb(0..15)*32 + lane
//   regs = W[n][c], W[n][c+4], W[n][c+8], W[n][c+12]
//   n = ntile*128+cb*8+(lane>>2), c = kt*16+(lane&3)
__device__ float W_packed[(size_t)NT*64*2048];         // ~206 MB
__device__ float g_nll[BB*(TT-1)];
__device__ float part_m[(size_t)MTOT*NT];              // per-(row, ntile) lse partials
__device__ float part_s[(size_t)MTOT*NT];

// ---------------- helpers ----------------
__device__ __forceinline__ unsigned cvt_tf32(float x) {
    unsigned u; asm("cvt.rna.tf32.f32 %0, %1;" : "=r"(u) : "f"(x)); return u;
}
__device__ __forceinline__ void mma_tf32(float* c,
    unsigned a0, unsigned a1, unsigned a2, unsigned a3,
    unsigned b0, unsigned b1)
{
    asm volatile("mma.sync.aligned.m16n8k8.row.col.f32.tf32.tf32.f32 "
        "{%0,%1,%2,%3}, {%4,%5,%6,%7}, {%8,%9}, {%0,%1,%2,%3};"
        : "+f"(c[0]), "+f"(c[1]), "+f"(c[2]), "+f"(c[3])
        : "r"(a0), "r"(a1), "r"(a2), "r"(a3), "r"(b0), "r"(b1));
}
__device__ __forceinline__ void cp16(void* dst, const void* src) {
    unsigned s = (unsigned)__cvta_generic_to_shared(dst);
    asm volatile("cp.async.cg.shared.global [%0], [%1], 16;" :: "r"(s), "l"(src));
}
// -inf-safe (m, s) logsumexp-state combine; fixed order -> deterministic
__device__ __forceinline__ void lse_comb(float& m, float& s, float mo, float so) {
    float M = fmaxf(m, mo);
    if (M == -CUDART_INF_F) { m = M; s = 0.f; return; }
    s = s * __expf(m - M) + so * __expf(mo - M);
    m = M;
}

// ---------------- pack kernels ----------------
__global__ void __launch_bounds__(256)
pack_A_kernel(const float* __restrict__ src)
{
    int idx  = blockIdx.x * 256 + threadIdx.x;     // 16B unit id
    int tile = idx >> 9;                            // 512 units per kt16 tile
    int v    = idx & 511;
    int mtile = tile >> 6, kt = tile & 63;
    int block = v >> 6, rem = v & 63;
    int slab  = rem >> 5, lane = rem & 31;
    int grp = lane >> 2, tg = lane & 3;
    int r0 = mtile * 128 + block * 16 + grp;
    int c0 = kt * 16 + slab * 8 + tg;
    const float* p = src + (size_t)r0 * HH + c0;
    float4 o;
    o.x = __uint_as_float(cvt_tf32(p[0]));
    o.y = __uint_as_float(cvt_tf32(p[8 * HH]));
    o.z = __uint_as_float(cvt_tf32(p[4]));
    o.w = __uint_as_float(cvt_tf32(p[8 * HH + 4]));
    ((float4*)A_packed)[idx] = o;
}

__global__ void __launch_bounds__(256)
pack_W_kernel(const float* __restrict__ src)
{
    int idx  = blockIdx.x * 256 + threadIdx.x;
    int tile = idx >> 9;
    int v    = idx & 511;
    int ntile = tile >> 6, kt = tile & 63;
    int cb = v >> 5, lane = v & 31;
    int grp = lane >> 2, tg = lane & 3;
    int n = ntile * 128 + cb * 8 + grp;
    int c = kt * 16 + tg;
    float4 o = make_float4(0.f, 0.f, 0.f, 0.f);
    if (n < VV) {
        const float* p = src + (size_t)n * HH + c;
        o.x = __uint_as_float(cvt_tf32(p[0]));
        o.y = __uint_as_float(cvt_tf32(p[4]));
        o.z = __uint_as_float(cvt_tf32(p[8]));
        o.w = __uint_as_float(cvt_tf32(p[12]));
    }
    ((float4*)W_packed)[idx] = o;
}

// ---------------- GEMM + fused lse partials ----------------
// CTA tile 256x128, 8 warps m64n64. Stage: [A lo 8KB][A hi 8KB][B 8KB].
__global__ void __launch_bounds__(NTHREADS, 1)
gemm_tf32_kernel(float* __restrict__ C)
{
    extern __shared__ char smem[];
    __shared__ float sbm[2][256], sbs[2][256];   // [warpN][local row]

    const int bm = blockIdx.x;     // M tile of 256 (fast dim)
    const int bn = blockIdx.y;     // N tile of 128
    const int tid = threadIdx.x;
    const int lane = tid & 31;
    const int warp = tid >> 5;
    const int warpM = warp >> 1;   // 0..3 -> 64 rows each
    const int warpN = warp & 1;    // 0..1 -> 64 cols each
    const int grp = lane >> 2, tg = lane & 3;

    const char* Abase0 = (const char*)A_packed + (size_t)(2 * bm)     * 64 * A_U;
    const char* Abase1 = (const char*)A_packed + (size_t)(2 * bm + 1) * 64 * A_U;
    const char* Bbase  = (const char*)W_packed + (size_t)bn * 64 * B_U;

    float acc[4][8][4];
    #pragma unroll
    for (int i = 0; i < 4; i++)
        #pragma unroll
        for (int j = 0; j < 8; j++)
            #pragma unroll
            for (int k = 0; k < 4; k++) acc[i][j][k] = 0.f;

    // 1536 x 16B chunks per stage, 6 per thread
    auto load_stage = [&](int kt) {
        char* stg = smem + (kt & (NST - 1)) * ST;
        const char* a0 = Abase0 + (size_t)kt * A_U;
        const char* a1 = Abase1 + (size_t)kt * A_U;
        const char* b_ = Bbase  + (size_t)kt * B_U;
        #pragma unroll
        for (int i = 0; i < 2; i++) {
            int j = tid + i * NTHREADS;            // 0..511
            cp16(stg + j * 16, a0 + j * 16);
        }
        #pragma unroll
        for (int i = 0; i < 2; i++) {
            int j = tid + i * NTHREADS;
            cp16(stg + A_U + j * 16, a1 + j * 16);
        }
        #pragma unroll
        for (int i = 0; i < 2; i++) {
            int j = tid + i * NTHREADS;
            cp16(stg + 2 * A_U + j * 16, b_ + j * 16);
        }
        asm volatile("cp.async.commit_group;");
    };

    #pragma unroll
    for (int s = 0; s < NST - 1; s++) load_stage(s);   // stages 0..6

    #pragma unroll 1
    for (int kt = 0; kt < NK; kt++) {
        // stage kt complete (tail: fewer groups remain outstanding)
        if (kt <= NK - NST + 1)      asm volatile("cp.async.wait_group 6;");
        else if (kt == NK - 6)       asm volatile("cp.async.wait_group 5;");
        else if (kt == NK - 5)       asm volatile("cp.async.wait_group 4;");
        else if (kt == NK - 4)       asm volatile("cp.async.wait_group 3;");
        else if (kt == NK - 3)       asm volatile("cp.async.wait_group 2;");
        else if (kt == NK - 2)       asm volatile("cp.async.wait_group 1;");
        else                         asm volatile("cp.async.wait_group 0;");
        __syncthreads();   // stage kt visible; stage (kt-1) reads finished

        if (kt + NST - 1 < NK) load_stage(kt + NST - 1);   // slot freed last iter

        const char* stg = smem + (kt & (NST - 1)) * ST;
        // A: warpM 0..3 -> half (0..1) + 4-block group within the 128-row tile
        const char* sA = stg + (warpM >> 1) * A_U + (size_t)((warpM & 1) * 4) * 1024
                             + lane * 16;
        const char* sB = stg + 2 * A_U + (size_t)(warpN * 8) * 512 + lane * 16;

        uint4 bf[8];
        #pragma unroll
        for (int nt = 0; nt < 8; nt++)
            bf[nt] = *(const uint4*)(sB + nt * 512);

        #pragma unroll
        for (int slab = 0; slab < 2; slab++) {
            uint4 af[4];
            #pragma unroll
            for (int mt = 0; mt < 4; mt++)
                af[mt] = *(const uint4*)(sA + mt * 1024 + slab * 512);
            #pragma unroll
            for (int mt = 0; mt < 4; mt++)
                #pragma unroll
                for (int nt = 0; nt < 8; nt++) {
                    unsigned b0 = slab ? bf[nt].z : bf[nt].x;
                    unsigned b1 = slab ? bf[nt].w : bf[nt].y;
                    mma_tf32(acc[mt][nt], af[mt].x, af[mt].y, af[mt].z, af[mt].w, b0, b1);
                }
        }
    }

    // ---- epilogue: C store + per-thread lse over own cols ----
    float lm[4][2], ls[4][2];
    #pragma unroll
    for (int mt = 0; mt < 4; mt++)
        #pragma unroll
        for (int sub = 0; sub < 2; sub++) { lm[mt][sub] = -CUDART_INF_F; ls[mt][sub] = 0.f; }

    #pragma unroll
    for (int mt = 0; mt < 4; mt++) {
        const int r0 = bm * TM + warpM * 64 + mt * 16 + grp;
        #pragma unroll
        for (int nt = 0; nt < 8; nt++) {
            const int c0 = bn * TN + warpN * 64 + nt * 8 + tg * 2;
            if (c0 < VV) {
                size_t base  = (size_t)r0 * VV + c0;
                size_t base2 = base + (size_t)8 * VV;
                C[base]  = acc[mt][nt][0];
                C[base2] = acc[mt][nt][2];
                if (c0 + 1 < VV) {
                    C[base + 1]  = acc[mt][nt][1];
                    C[base2 + 1] = acc[mt][nt][3];
                }
            }
            #pragma unroll
            for (int sub = 0; sub < 2; sub++) {
                #pragma unroll
                for (int cp = 0; cp < 2; cp++) {
                    if (c0 + cp < VV) {
                        float x = acc[mt][nt][sub * 2 + cp];
                        float& m = lm[mt][sub];
                        float& s = ls[mt][sub];
                        if (x > m) { s = s * __expf(m - x) + 1.f; m = x; }
                        else       { s += __expf(x - m); }
                    }
                }
            }
        }
    }
    // quad combine (lanes sharing grp, tg=0..3)
    #pragma unroll
    for (int mt = 0; mt < 4; mt++)
        #pragma unroll
        for (int sub = 0; sub < 2; sub++) {
            #pragma unroll
            for (int off = 1; off <= 2; off <<= 1) {
                float mo = __shfl_xor_sync(0xffffffffu, lm[mt][sub], off);
                float so = __shfl_xor_sync(0xffffffffu, ls[mt][sub], off);
                lse_comb(lm[mt][sub], ls[mt][sub], mo, so);
            }
        }
    if (tg == 0) {
        #pragma unroll
        for (int mt = 0; mt < 4; mt++)
            #pragma unroll
            for (int sub = 0; sub < 2; sub++) {
                int rl = warpM * 64 + mt * 16 + sub * 8 + grp;
                sbm[warpN][rl] = lm[mt][sub];
                sbs[warpN][rl] = ls[mt][sub];
            }
    }
    __syncthreads();
    // one thread per local row: combine the two warpN halves, write partials
    {
        float m = sbm[0][tid], s = sbs[0][tid];
        lse_comb(m, s, sbm[1][tid], sbs[1][tid]);
        size_t idx = (size_t)(bm * TM + tid) * NT + bn;
        part_m[idx] = m;
        part_s[idx] = s;
    }
}

// ---------------- loss from partials ----------------
__global__ void __launch_bounds__(128)
loss_partial_kernel(const float* __restrict__ C, const int* __restrict__ labels)
{
    const int r = blockIdx.x;               // 0..4093 shifted rows
    const int b = r / (TT - 1);
    const int t = r - b * (TT - 1);
    const int row = b * TT + t;

    float m = -CUDART_INF_F, s = 0.f;
    for (int j = threadIdx.x; j < NT; j += 128)
        lse_comb(m, s, part_m[(size_t)row * NT + j], part_s[(size_t)row * NT + j]);

    #pragma unroll
    for (int o = 16; o; o >>= 1) {
        float mo = __shfl_down_sync(0xffffffffu, m, o);
        float so = __shfl_down_sync(0xffffffffu, s, o);
        lse_comb(m, s, mo, so);
    }
    __shared__ float sm_[4], ss_[4];
    const int lane = threadIdx.x & 31, w = threadIdx.x >> 5;
    if (lane == 0) { sm_[w] = m; ss_[w] = s; }
    __syncthreads();
    if (threadIdx.x == 0) {
        m = sm_[0]; s = ss_[0];
        lse_comb(m, s, sm_[1], ss_[1]);
        lse_comb(m, s, sm_[2], ss_[2]);
        lse_comb(m, s, sm_[3], ss_[3]);
        int lbl = labels[row + 1];
        if (lbl < 0) lbl = 0;
        if (lbl >= VV) lbl = VV - 1;
        g_nll[r] = m + __logf(s) - C[(size_t)row * VV + lbl];
    }
}

__global__ void __launch_bounds__(256)
loss_reduce_kernel(float* __restrict__ out_loss)
{
    __shared__ float sh[256];
    float v = 0.f;
    for (int i = threadIdx.x; i < BB * (TT - 1); i += 256) v += g_nll[i];
    sh[threadIdx.x] = v;
    __syncthreads();
    for (int st = 128; st; st >>= 1) {
        if (threadIdx.x < st) sh[threadIdx.x] += sh[threadIdx.x + st];
        __syncthreads();
    }
    if (threadIdx.x == 0) *out_loss = sh[0] / (float)(BB * (TT - 1));
}

// ---------------- launch ----------------
extern "C" void kernel_launch(void* const* d_in, const int* in_sizes, int n_in,
                              void* d_out, int out_size)
{
    const float* hidden = nullptr;
    const float* weight = nullptr;
    const int*   labels = nullptr;
    for (int i = 0; i < n_in; i++) {
        if      (in_sizes[i] == MTOT * HH) hidden = (const float*)d_in[i];
        else if (in_sizes[i] == VV * HH)   weight = (const float*)d_in[i];
        else if (in_sizes[i] == BB * TT)   labels = (const int*)d_in[i];
    }
    float* out = (float*)d_out;

    cudaFuncSetAttribute(gemm_tf32_kernel,
                         cudaFuncAttributeMaxDynamicSharedMemorySize, SMEM_TOTAL);

    pack_A_kernel<<<(MTOT * HH / 4) / 256, 256>>>(hidden);
    pack_W_kernel<<<(NT * 64 * 512) / 256, 256>>>(weight);

    dim3 grid(MTOT / TM, NT);          // (16, 393)
    gemm_tf32_kernel<<<grid, NTHREADS, SMEM_TOTAL>>>(out);

    loss_partial_kernel<<<BB * (TT - 1), 128>>>(out, labels);
    loss_reduce_kernel<<<1, 256>>>(out + (size_t)out_size - 1);
}

// round 11
// speedup vs baseline: 1.0017x; 1.0017x over previous
#include <cuda_runtime.h>
#include <math_constants.h>
#include <cstdint>
#include <cstddef>

// ---------------- Problem constants ----------------
#define BB 2
#define TT 2048
#define HH 1024
#define VV 50257
#define MTOT (BB*TT)          // 4096
#define NT 393                // ceil(50257/128) N tiles

// ---------------- GEMM tiling (R7 shape + cluster-4 B multicast) ----------------
#define TM 128
#define TN 128
#define NST 4                 // pipeline stages (TK=16 each)
#define NK 64                 // K iterations
#define NTHREADS 128          // 4 warps, each m64n64
#define CLU 4                 // cluster size along bm

#define A_U 8192              // A bytes per stage
#define B_U 8192              // B bytes per stage
#define BQ  (B_U/CLU)         // 2048 multicast quarter
#define ST  (A_U+B_U)         // 16384
#define SMEM_TOTAL (NST*ST)   // 65536 dynamic

// ---------------- device scratch ----------------
// A_packed: [mtile 0..31][kt 0..63] tiles of 8KB, mma fragment order (see pack_A)
__device__ float A_packed[MTOT*HH];                    // 16 MB
// W_packed: [ntile 0..392][kt 0..63] tiles of 8KB (see pack_W)
__device__ float W_packed[(size_t)NT*64*2048];         // ~206 MB
__device__ float g_nll[BB*(TT-1)];
__device__ float part_m[(size_t)MTOT*NT];
__device__ float part_s[(size_t)MTOT*NT];

// ---------------- helpers ----------------
__device__ __forceinline__ unsigned cvt_tf32(float x) {
    unsigned u; asm("cvt.rna.tf32.f32 %0, %1;" : "=r"(u) : "f"(x)); return u;
}
__device__ __forceinline__ void mma_tf32(float* c,
    unsigned a0, unsigned a1, unsigned a2, unsigned a3,
    unsigned b0, unsigned b1)
{
    asm volatile("mma.sync.aligned.m16n8k8.row.col.f32.tf32.tf32.f32 "
        "{%0,%1,%2,%3}, {%4,%5,%6,%7}, {%8,%9}, {%0,%1,%2,%3};"
        : "+f"(c[0]), "+f"(c[1]), "+f"(c[2]), "+f"(c[3])
        : "r"(a0), "r"(a1), "r"(a2), "r"(a3), "r"(b0), "r"(b1));
}
__device__ __forceinline__ void cp16(void* dst, const void* src) {
    unsigned s = (unsigned)__cvta_generic_to_shared(dst);
    asm volatile("cp.async.cg.shared.global [%0], [%1], 16;" :: "r"(s), "l"(src));
}
__device__ __forceinline__ uint32_t smem_u32(const void* p) {
    uint32_t a;
    asm("{ .reg .u64 t; cvta.to.shared.u64 t, %1; cvt.u32.u64 %0, t; }" : "=r"(a) : "l"(p));
    return a;
}
__device__ __forceinline__ void mbar_init(uint32_t mbar, uint32_t cnt) {
    asm volatile("mbarrier.init.shared.b64 [%0], %1;" :: "r"(mbar), "r"(cnt) : "memory");
}
__device__ __forceinline__ void mbar_expect_tx(uint32_t mbar, uint32_t bytes) {
    asm volatile("mbarrier.arrive.expect_tx.shared.b64 _, [%0], %1;"
                 :: "r"(mbar), "r"(bytes) : "memory");
}
__device__ __forceinline__ void mbar_wait(uint32_t mbar, uint32_t parity) {
    asm volatile(
        "{\n\t.reg .pred P1;\n\t"
        "WAIT_LOOP_%=:\n\t"
        "mbarrier.try_wait.parity.acquire.cta.shared::cta.b64 P1, [%0], %1, 0x989680;\n\t"
        "@P1 bra.uni WAIT_DONE_%=;\n\t"
        "bra.uni WAIT_LOOP_%=;\n\t"
        "WAIT_DONE_%=:\n\t}"
        :: "r"(mbar), "r"(parity) : "memory");
}
__device__ __forceinline__ void mbar_arrive_remote(uint32_t local_addr, uint32_t rank) {
    asm volatile(
        "{\n\t.reg .b32 r;\n\t"
        "mapa.shared::cluster.u32 r, %0, %1;\n\t"
        "mbarrier.arrive.shared::cluster.b64 _, [r];\n\t}"
        :: "r"(local_addr), "r"(rank) : "memory");
}
__device__ __forceinline__ void bulk_g2s_mc(uint32_t dst, const void* src, uint32_t bytes,
                                            uint32_t mbar, uint16_t mask) {
    asm volatile("cp.async.bulk.shared::cluster.global.mbarrier::complete_tx::bytes"
                 ".multicast::cluster [%0], [%1], %2, [%3], %4;"
                 :: "r"(dst), "l"(src), "r"(bytes), "r"(mbar), "h"(mask) : "memory");
}
// -inf-safe (m, s) logsumexp-state combine; fixed order -> deterministic
__device__ __forceinline__ void lse_comb(float& m, float& s, float mo, float so) {
    float M = fmaxf(m, mo);
    if (M == -CUDART_INF_F) { m = M; s = 0.f; return; }
    s = s * __expf(m - M) + so * __expf(mo - M);
    m = M;
}

// ---------------- pack kernels ----------------
__global__ void __launch_bounds__(256)
pack_A_kernel(const float* __restrict__ src)
{
    int idx  = blockIdx.x * 256 + threadIdx.x;     // 16B unit id
    int tile = idx >> 9;                            // 512 units per kt16 tile
    int v    = idx & 511;
    int mtile = tile >> 6, kt = tile & 63;
    int block = v >> 6, rem = v & 63;
    int slab  = rem >> 5, lane = rem & 31;
    int grp = lane >> 2, tg = lane & 3;
    int r0 = mtile * 128 + block * 16 + grp;
    int c0 = kt * 16 + slab * 8 + tg;
    const float* p = src + (size_t)r0 * HH + c0;
    float4 o;
    o.x = __uint_as_float(cvt_tf32(p[0]));
    o.y = __uint_as_float(cvt_tf32(p[8 * HH]));
    o.z = __uint_as_float(cvt_tf32(p[4]));
    o.w = __uint_as_float(cvt_tf32(p[8 * HH + 4]));
    ((float4*)A_packed)[idx] = o;
}

__global__ void __launch_bounds__(256)
pack_W_kernel(const float* __restrict__ src)
{
    int idx  = blockIdx.x * 256 + threadIdx.x;
    int tile = idx >> 9;
    int v    = idx & 511;
    int ntile = tile >> 6, kt = tile & 63;
    int cb = v >> 5, lane = v & 31;
    int grp = lane >> 2, tg = lane & 3;
    int n = ntile * 128 + cb * 8 + grp;
    int c = kt * 16 + tg;
    float4 o = make_float4(0.f, 0.f, 0.f, 0.f);
    if (n < VV) {
        const float* p = src + (size_t)n * HH + c;
        o.x = __uint_as_float(cvt_tf32(p[0]));
        o.y = __uint_as_float(cvt_tf32(p[4]));
        o.z = __uint_as_float(cvt_tf32(p[8]));
        o.w = __uint_as_float(cvt_tf32(p[12]));
    }
    ((float4*)W_packed)[idx] = o;
}

// ---------------- GEMM + fused lse partials ----------------
__global__ void __launch_bounds__(NTHREADS, 2) __cluster_dims__(CLU, 1, 1)
gemm_tf32_kernel(float* __restrict__ C)
{
    extern __shared__ char smem[];
    __shared__ float sbm[2][128], sbs[2][128];
    __shared__ __align__(8) uint64_t mbar_full[NST], mbar_empty[NST];

    const int bm = blockIdx.x;     // M tile (fast dim; cluster of 4 shares bn)
    const int bn = blockIdx.y;     // N tile
    const int tid = threadIdx.x;
    const int lane = tid & 31;
    const int warp = tid >> 5;
    const int warpM = warp >> 1;   // 0..1 -> 64 rows
    const int warpN = warp & 1;    // 0..1 -> 64 cols
    const int grp = lane >> 2, tg = lane & 3;
    const uint32_t rank = (uint32_t)(bm & (CLU - 1));

    const uint32_t fullb  = smem_u32(&mbar_full[0]);
    const uint32_t emptyb = smem_u32(&mbar_empty[0]);

    const char* Abase = (const char*)A_packed + (size_t)bm * 64 * A_U;
    const char* Bbase = (const char*)W_packed + (size_t)bn * 64 * B_U;

    if (tid == 0) {
        #pragma unroll
        for (int s = 0; s < NST; s++) {
            mbar_init(fullb + s * 8, 1);        // expect_tx arrival
            mbar_init(emptyb + s * 8, CLU);     // one arrive per cluster CTA
        }
    }
    __syncthreads();
    asm volatile("barrier.cluster.arrive.aligned;" ::: "memory");
    asm volatile("barrier.cluster.wait.aligned;"   ::: "memory");

    float acc[4][8][4];
    #pragma unroll
    for (int i = 0; i < 4; i++)
        #pragma unroll
        for (int j = 0; j < 8; j++)
            #pragma unroll
            for (int k = 0; k < 4; k++) acc[i][j][k] = 0.f;

    // A stage: 512 x 16B chunks by all threads (4 per thread)
    auto load_A = [&](int kt) {
        char* stg = smem + (kt & (NST - 1)) * ST;
        const char* asrc = Abase + (size_t)kt * A_U;
        #pragma unroll
        for (int i = 0; i < 4; i++) {
            int j = tid + i * NTHREADS;
            cp16(stg + j * 16, asrc + j * 16);
        }
        asm volatile("cp.async.commit_group;");
    };
    // B stage: tid0 multicasts this CTA's 2KB quarter to the whole cluster
    auto produce_B = [&](int kt) {
        const int s = kt & (NST - 1);
        mbar_wait(emptyb + s * 8, 1u ^ (((unsigned)kt / NST) & 1u));
        mbar_expect_tx(fullb + s * 8, B_U);
        uint32_t dst = smem_u32(smem) + s * ST + A_U + rank * BQ;
        bulk_g2s_mc(dst, Bbase + (size_t)kt * B_U + rank * BQ, BQ,
                    fullb + s * 8, (uint16_t)0xF);
    };

    load_A(0); load_A(1); load_A(2);
    if (tid == 0) { produce_B(0); produce_B(1); produce_B(2); }

    #pragma unroll 1
    for (int kt = 0; kt < NK; kt++) {
        if (kt < NK - 2)        asm volatile("cp.async.wait_group 2;");
        else if (kt == NK - 2)  asm volatile("cp.async.wait_group 1;");
        else                    asm volatile("cp.async.wait_group 0;");
        mbar_wait(fullb + (kt & (NST - 1)) * 8, ((unsigned)kt / NST) & 1u);
        __syncthreads();   // stage kt visible; stage (kt-1) reads finished locally

        if (tid == 0 && kt >= 1) {
            const uint32_t fs = emptyb + ((kt - 1) & (NST - 1)) * 8;
            #pragma unroll
            for (uint32_t r_ = 0; r_ < CLU; r_++) mbar_arrive_remote(fs, r_);
        }
        if (kt + 3 < NK) {
            load_A(kt + 3);                     // slot freed locally last iter
            if (tid == 0) produce_B(kt + 3);    // waits cluster-wide slot free
        }

        const char* stg = smem + (kt & (NST - 1)) * ST;
        const char* sA = stg + (size_t)(warpM * 4) * 1024 + lane * 16;
        const char* sB = stg + A_U + (size_t)(warpN * 8) * 512 + lane * 16;

        uint4 bf[8];
        #pragma unroll
        for (int nt = 0; nt < 8; nt++)
            bf[nt] = *(const uint4*)(sB + nt * 512);

        #pragma unroll
        for (int slab = 0; slab < 2; slab++) {
            uint4 af[4];
            #pragma unroll
            for (int mt = 0; mt < 4; mt++)
                af[mt] = *(const uint4*)(sA + mt * 1024 + slab * 512);
            #pragma unroll
            for (int mt = 0; mt < 4; mt++)
                #pragma unroll
                for (int nt = 0; nt < 8; nt++) {
                    unsigned b0 = slab ? bf[nt].z : bf[nt].x;
                    unsigned b1 = slab ? bf[nt].w : bf[nt].y;
                    mma_tf32(acc[mt][nt], af[mt].x, af[mt].y, af[mt].z, af[mt].w, b0, b1);
                }
        }
    }

    // ---- epilogue: C store + per-thread lse over own cols ----
    float lm[4][2], ls[4][2];
    #pragma unroll
    for (int mt = 0; mt < 4; mt++)
        #pragma unroll
        for (int sub = 0; sub < 2; sub++) { lm[mt][sub] = -CUDART_INF_F; ls[mt][sub] = 0.f; }

    #pragma unroll
    for (int mt = 0; mt < 4; mt++) {
        const int r0 = bm * TM + warpM * 64 + mt * 16 + grp;
        #pragma unroll
        for (int nt = 0; nt < 8; nt++) {
            const int c0 = bn * TN + warpN * 64 + nt * 8 + tg * 2;
            if (c0 < VV) {
                size_t base  = (size_t)r0 * VV + c0;
                size_t base2 = base + (size_t)8 * VV;
                C[base]  = acc[mt][nt][0];
                C[base2] = acc[mt][nt][2];
                if (c0 + 1 < VV) {
                    C[base + 1]  = acc[mt][nt][1];
                    C[base2 + 1] = acc[mt][nt][3];
                }
            }
            #pragma unroll
            for (int sub = 0; sub < 2; sub++) {
                #pragma unroll
                for (int cp = 0; cp < 2; cp++) {
                    if (c0 + cp < VV) {
                        float x = acc[mt][nt][sub * 2 + cp];
                        float& m = lm[mt][sub];
                        float& s = ls[mt][sub];
                        if (x > m) { s = s * __expf(m - x) + 1.f; m = x; }
                        else       { s += __expf(x - m); }
                    }
                }
            }
        }
    }
    #pragma unroll
    for (int mt = 0; mt < 4; mt++)
        #pragma unroll
        for (int sub = 0; sub < 2; sub++) {
            #pragma unroll
            for (int off = 1; off <= 2; off <<= 1) {
                float mo = __shfl_xor_sync(0xffffffffu, lm[mt][sub], off);
                float so = __shfl_xor_sync(0xffffffffu, ls[mt][sub], off);
                lse_comb(lm[mt][sub], ls[mt][sub], mo, so);
            }
        }
    if (tg == 0) {
        #pragma unroll
        for (int mt = 0; mt < 4; mt++)
            #pragma unroll
            for (int sub = 0; sub < 2; sub++) {
                int rl = warpM * 64 + mt * 16 + sub * 8 + grp;
                sbm[warpN][rl] = lm[mt][sub];
                sbs[warpN][rl] = ls[mt][sub];
            }
    }
    __syncthreads();
    {
        float m = sbm[0][tid], s = sbs[0][tid];
        lse_comb(m, s, sbm[1][tid], sbs[1][tid]);
        size_t idx = (size_t)(bm * TM + tid) * NT + bn;
        part_m[idx] = m;
        part_s[idx] = s;
    }

    // no CTA exits while peers may still touch its smem / barriers
    asm volatile("barrier.cluster.arrive.aligned;" ::: "memory");
    asm volatile("barrier.cluster.wait.aligned;"   ::: "memory");
}

// ---------------- loss from partials ----------------
__global__ void __launch_bounds__(128)
loss_partial_kernel(const float* __restrict__ C, const int* __restrict__ labels)
{
    const int r = blockIdx.x;               // 0..4093 shifted rows
    const int b = r / (TT - 1);
    const int t = r - b * (TT - 1);
    const int row = b * TT + t;

    float m = -CUDART_INF_F, s = 0.f;
    for (int j = threadIdx.x; j < NT; j += 128)
        lse_comb(m, s, part_m[(size_t)row * NT + j], part_s[(size_t)row * NT + j]);

    #pragma unroll
    for (int o = 16; o; o >>= 1) {
        float mo = __shfl_down_sync(0xffffffffu, m, o);
        float so = __shfl_down_sync(0xffffffffu, s, o);
        lse_comb(m, s, mo, so);
    }
    __shared__ float sm_[4], ss_[4];
    const int lane = threadIdx.x & 31, w = threadIdx.x >> 5;
    if (lane == 0) { sm_[w] = m; ss_[w] = s; }
    __syncthreads();
    if (threadIdx.x == 0) {
        m = sm_[0]; s = ss_[0];
        lse_comb(m, s, sm_[1], ss_[1]);
        lse_comb(m, s, sm_[2], ss_[2]);
        lse_comb(m, s, sm_[3], ss_[3]);
        int lbl = labels[row + 1];
        if (lbl < 0) lbl = 0;
        if (lbl >= VV) lbl = VV - 1;
        g_nll[r] = m + __logf(s) - C[(size_t)row * VV + lbl];
    }
}

__global__ void __launch_bounds__(256)
loss_reduce_kernel(float* __restrict__ out_loss)
{
    __shared__ float sh[256];
    float v = 0.f;
    for (int i = threadIdx.x; i < BB * (TT - 1); i += 256) v += g_nll[i];
    sh[threadIdx.x] = v;
    __syncthreads();
    for (int st = 128; st; st >>= 1) {
        if (threadIdx.x < st) sh[threadIdx.x] += sh[threadIdx.x + st];
        __syncthreads();
    }
    if (threadIdx.x == 0) *out_loss = sh[0] / (float)(BB * (TT - 1));
}

// ---------------- launch ----------------
extern "C" void kernel_launch(void* const* d_in, const int* in_sizes, int n_in,
                              void* d_out, int out_size)
{
    const float* hidden = nullptr;
    const float* weight = nullptr;
    const int*   labels = nullptr;
    for (int i = 0; i < n_in; i++) {
        if      (in_sizes[i] == MTOT * HH) hidden = (const float*)d_in[i];
        else if (in_sizes[i] == VV * HH)   weight = (const float*)d_in[i];
        else if (in_sizes[i] == BB * TT)   labels = (const int*)d_in[i];
    }
    float* out = (float*)d_out;

    cudaFuncSetAttribute(gemm_tf32_kernel,
                         cudaFuncAttributeMaxDynamicSharedMemorySize, SMEM_TOTAL);

    pack_A_kernel<<<(MTOT * HH / 4) / 256, 256>>>(hidden);
    pack_W_kernel<<<(NT * 64 * 512) / 256, 256>>>(weight);

    dim3 grid(MTOT / TM, NT);          // (32, 393); cluster 4 along x
    gemm_tf32_kernel<<<grid, NTHREADS, SMEM_TOTAL>>>(out);

    loss_partial_kernel<<<BB * (TT - 1), 128>>>(out, labels);
    loss_reduce_kernel<<<1, 256>>>(out + (size_t)out_size - 1);
}

// round 12
// speedup vs baseline: 1.9789x; 1.9756x over previous
#include <cuda_runtime.h>
#include <cuda_fp16.h>
#include <math_constants.h>
#include <cstdint>
#include <cstddef>

// ---------------- Problem constants ----------------
#define BB 2
#define TT 2048
#define HH 1024
#define VV 50257
#define MTOT (BB*TT)          // 4096
#define NT 393                // ceil(50257/128) N tiles

// ---------------- GEMM tiling (R7 shape, fp16 operands) ----------------
#define TM 128
#define TN 128
#define NST 4                 // pipeline stages (TK=16 each)
#define NK 64                 // K iterations
#define NTHREADS 128          // 4 warps, each m64n64

#define A_U 4096              // A bytes per kt16 stage (128x16 fp16)
#define B_U 4096              // B bytes per kt16 stage (128x16 fp16)
#define ST  (A_U+B_U)         // 8192
#define SMEM_TOTAL (NST*ST)   // 32768 dynamic

// ---------------- device scratch ----------------
// A_half: [mtile 0..31][kt 0..63] tiles of 4KB; unit16B u = block(0..7)*32+lane:
//   {A[r0][c0],A[r0][c0+1]}, {A[r0+8][c0],A[r0+8][c0+1]},
//   {A[r0][c0+8],A[r0][c0+9]}, {A[r0+8][c0+8],A[r0+8][c0+9]}
//   r0 = mtile*128+block*16+(lane>>2), c0 = kt*16+(lane&3)*2
__device__ __half A_half[MTOT*HH];                     // 8 MB
// W_half: [ntile 0..392][kt 0..63] tiles of 4KB; unit16B u = pair(0..7)*32+lane:
//   ne = ntile*128+(2*pair)*8+(lane>>2), no = ne+8, c0 = kt*16+(lane&3)*2
//   {W[ne][c0],W[ne][c0+1]}, {W[ne][c0+8],W[ne][c0+9]},
//   {W[no][c0],W[no][c0+1]}, {W[no][c0+8],W[no][c0+9]}
__device__ __half W_half[(size_t)NT*131072];           // ~103 MB
__device__ float g_nll[BB*(TT-1)];
__device__ float part_m[(size_t)MTOT*NT];
__device__ float part_s[(size_t)MTOT*NT];

// ---------------- helpers ----------------
__device__ __forceinline__ unsigned pack_h2(float lo, float hi) {
    __half2 h = __floats2half2_rn(lo, hi);
    return *reinterpret_cast<unsigned*>(&h);
}
__device__ __forceinline__ void mma_f16(float* c,
    unsigned a0, unsigned a1, unsigned a2, unsigned a3,
    unsigned b0, unsigned b1)
{
    asm volatile("mma.sync.aligned.m16n8k16.row.col.f32.f16.f16.f32 "
        "{%0,%1,%2,%3}, {%4,%5,%6,%7}, {%8,%9}, {%0,%1,%2,%3};"
        : "+f"(c[0]), "+f"(c[1]), "+f"(c[2]), "+f"(c[3])
        : "r"(a0), "r"(a1), "r"(a2), "r"(a3), "r"(b0), "r"(b1));
}
__device__ __forceinline__ void cp16(void* dst, const void* src) {
    unsigned s = (unsigned)__cvta_generic_to_shared(dst);
    asm volatile("cp.async.cg.shared.global [%0], [%1], 16;" :: "r"(s), "l"(src));
}
// -inf-safe (m, s) logsumexp-state combine; fixed order -> deterministic
__device__ __forceinline__ void lse_comb(float& m, float& s, float mo, float so) {
    float M = fmaxf(m, mo);
    if (M == -CUDART_INF_F) { m = M; s = 0.f; return; }
    s = s * __expf(m - M) + so * __expf(mo - M);
    m = M;
}

// ---------------- pack kernels ----------------
__global__ void __launch_bounds__(256)
pack_A_kernel(const float* __restrict__ src)
{
    int idx  = blockIdx.x * 256 + threadIdx.x;     // 16B unit id (32*64*256 total)
    int tile = idx >> 8;                            // 256 units per kt16 tile
    int v    = idx & 255;
    int mtile = tile >> 6, kt = tile & 63;
    int block = v >> 5, lane = v & 31;
    int grp = lane >> 2, tg = lane & 3;
    int r0 = mtile * 128 + block * 16 + grp;
    int c0 = kt * 16 + tg * 2;
    const float* p = src + (size_t)r0 * HH + c0;
    uint4 o;
    o.x = pack_h2(p[0],          p[1]);
    o.y = pack_h2(p[8 * HH],     p[8 * HH + 1]);
    o.z = pack_h2(p[8],          p[9]);
    o.w = pack_h2(p[8 * HH + 8], p[8 * HH + 9]);
    ((uint4*)A_half)[idx] = o;
}

__global__ void __launch_bounds__(256)
pack_W_kernel(const float* __restrict__ src)
{
    int idx  = blockIdx.x * 256 + threadIdx.x;     // 16B unit id (393*64*256 total)
    int tile = idx >> 8;
    int v    = idx & 255;
    int ntile = tile >> 6, kt = tile & 63;
    int pair = v >> 5, lane = v & 31;
    int grp = lane >> 2, tg = lane & 3;
    int ne = ntile * 128 + pair * 16 + grp;        // even n8 chunk row
    int no = ne + 8;                               // odd n8 chunk row
    int c0 = kt * 16 + tg * 2;
    uint4 o = make_uint4(0u, 0u, 0u, 0u);
    if (ne < VV) {
        const float* pe = src + (size_t)ne * HH + c0;
        o.x = pack_h2(pe[0], pe[1]);
        o.y = pack_h2(pe[8], pe[9]);
    }
    if (no < VV) {
        const float* po = src + (size_t)no * HH + c0;
        o.z = pack_h2(po[0], po[1]);
        o.w = pack_h2(po[8], po[9]);
    }
    ((uint4*)W_half)[idx] = o;
}

// ---------------- GEMM + fused lse partials ----------------
__global__ void __launch_bounds__(NTHREADS, 2)
gemm_f16_kernel(float* __restrict__ C)
{
    extern __shared__ char smem[];
    __shared__ float sbm[2][128], sbs[2][128];   // [warpN][local row]

    const int bm = blockIdx.x;     // M tile (fast dim -> A stays L2 hot)
    const int bn = blockIdx.y;     // N tile
    const int tid = threadIdx.x;
    const int lane = tid & 31;
    const int warp = tid >> 5;
    const int warpM = warp >> 1;   // 0..1 -> 64 rows
    const int warpN = warp & 1;    // 0..1 -> 64 cols
    const int grp = lane >> 2, tg = lane & 3;

    const char* Abase = (const char*)A_half + (size_t)bm * 64 * A_U;
    const char* Bbase = (const char*)W_half + (size_t)bn * 64 * B_U;

    float acc[4][8][4];
    #pragma unroll
    for (int i = 0; i < 4; i++)
        #pragma unroll
        for (int j = 0; j < 8; j++)
            #pragma unroll
            for (int k = 0; k < 4; k++) acc[i][j][k] = 0.f;

    // Stage: [A 4KB = 256 units][B 4KB = 256 units]; 4 units per thread.
    auto load_stage = [&](int kt) {
        char* stg = smem + (kt & (NST - 1)) * ST;
        const char* asrc = Abase + (size_t)kt * A_U;
        const char* bsrc = Bbase + (size_t)kt * B_U;
        #pragma unroll
        for (int i = 0; i < 2; i++) {
            int j = tid + i * NTHREADS;            // 0..255
            cp16(stg + j * 16, asrc + j * 16);
        }
        #pragma unroll
        for (int i = 0; i < 2; i++) {
            int j = tid + i * NTHREADS;
            cp16(stg + A_U + j * 16, bsrc + j * 16);
        }
        asm volatile("cp.async.commit_group;");
    };

    load_stage(0); load_stage(1); load_stage(2);

    #pragma unroll 1
    for (int kt = 0; kt < NK; kt++) {
        if (kt < NK - 2)        asm volatile("cp.async.wait_group 2;");
        else if (kt == NK - 2)  asm volatile("cp.async.wait_group 1;");
        else                    asm volatile("cp.async.wait_group 0;");
        __syncthreads();   // stage kt visible; stage (kt-1) reads finished

        if (kt + 3 < NK) load_stage(kt + 3);   // into the slot freed last iter

        const char* stg = smem + (kt & (NST - 1)) * ST;
        const char* sA = stg + (size_t)(warpM * 4) * 512 + lane * 16;
        const char* sB = stg + A_U + (size_t)(warpN * 4) * 512 + lane * 16;

        uint4 af[4], bf[4];
        #pragma unroll
        for (int mt = 0; mt < 4; mt++)
            af[mt] = *(const uint4*)(sA + mt * 512);
        #pragma unroll
        for (int pp = 0; pp < 4; pp++)
            bf[pp] = *(const uint4*)(sB + pp * 512);

        #pragma unroll
        for (int mt = 0; mt < 4; mt++)
            #pragma unroll
            for (int nt = 0; nt < 8; nt++) {
                unsigned b0 = (nt & 1) ? bf[nt >> 1].z : bf[nt >> 1].x;
                unsigned b1 = (nt & 1) ? bf[nt >> 1].w : bf[nt >> 1].y;
                mma_f16(acc[mt][nt], af[mt].x, af[mt].y, af[mt].z, af[mt].w, b0, b1);
            }
    }

    // ---- epilogue: C store + per-thread lse over own cols ----
    float lm[4][2], ls[4][2];
    #pragma unroll
    for (int mt = 0; mt < 4; mt++)
        #pragma unroll
        for (int sub = 0; sub < 2; sub++) { lm[mt][sub] = -CUDART_INF_F; ls[mt][sub] = 0.f; }

    #pragma unroll
    for (int mt = 0; mt < 4; mt++) {
        const int r0 = bm * TM + warpM * 64 + mt * 16 + grp;
        #pragma unroll
        for (int nt = 0; nt < 8; nt++) {
            const int c0 = bn * TN + warpN * 64 + nt * 8 + tg * 2;
            if (c0 < VV) {
                size_t base  = (size_t)r0 * VV + c0;
                size_t base2 = base + (size_t)8 * VV;
                C[base]  = acc[mt][nt][0];
                C[base2] = acc[mt][nt][2];
                if (c0 + 1 < VV) {
                    C[base + 1]  = acc[mt][nt][1];
                    C[base2 + 1] = acc[mt][nt][3];
                }
            }
            #pragma unroll
            for (int sub = 0; sub < 2; sub++) {
                #pragma unroll
                for (int cp = 0; cp < 2; cp++) {
                    if (c0 + cp < VV) {
                        float x = acc[mt][nt][sub * 2 + cp];
                        float& m = lm[mt][sub];
                        float& s = ls[mt][sub];
                        if (x > m) { s = s * __expf(m - x) + 1.f; m = x; }
                        else       { s += __expf(x - m); }
                    }
                }
            }
        }
    }
    // quad combine (lanes sharing grp, tg=0..3)
    #pragma unroll
    for (int mt = 0; mt < 4; mt++)
        #pragma unroll
        for (int sub = 0; sub < 2; sub++) {
            #pragma unroll
            for (int off = 1; off <= 2; off <<= 1) {
                float mo = __shfl_xor_sync(0xffffffffu, lm[mt][sub], off);
                float so = __shfl_xor_sync(0xffffffffu, ls[mt][sub], off);
                lse_comb(lm[mt][sub], ls[mt][sub], mo, so);
            }
        }
    if (tg == 0) {
        #pragma unroll
        for (int mt = 0; mt < 4; mt++)
            #pragma unroll
            for (int sub = 0; sub < 2; sub++) {
                int rl = warpM * 64 + mt * 16 + sub * 8 + grp;
                sbm[warpN][rl] = lm[mt][sub];
                sbs[warpN][rl] = ls[mt][sub];
            }
    }
    __syncthreads();
    // one thread per local row: combine the two warpN halves, write partials
    {
        float m = sbm[0][tid], s = sbs[0][tid];
        lse_comb(m, s, sbm[1][tid], sbs[1][tid]);
        size_t idx = (size_t)(bm * TM + tid) * NT + bn;
        part_m[idx] = m;
        part_s[idx] = s;
    }
}

// ---------------- loss from partials ----------------
__global__ void __launch_bounds__(128)
loss_partial_kernel(const float* __restrict__ C, const int* __restrict__ labels)
{
    const int r = blockIdx.x;               // 0..4093 shifted rows
    const int b = r / (TT - 1);
    const int t = r - b * (TT - 1);
    const int row = b * TT + t;

    float m = -CUDART_INF_F, s = 0.f;
    for (int j = threadIdx.x; j < NT; j += 128)
        lse_comb(m, s, part_m[(size_t)row * NT + j], part_s[(size_t)row * NT + j]);

    #pragma unroll
    for (int o = 16; o; o >>= 1) {
        float mo = __shfl_down_sync(0xffffffffu, m, o);
        float so = __shfl_down_sync(0xffffffffu, s, o);
        lse_comb(m, s, mo, so);
    }
    __shared__ float sm_[4], ss_[4];
    const int lane = threadIdx.x & 31, w = threadIdx.x >> 5;
    if (lane == 0) { sm_[w] = m; ss_[w] = s; }
    __syncthreads();
    if (threadIdx.x == 0) {
        m = sm_[0]; s = ss_[0];
        lse_comb(m, s, sm_[1], ss_[1]);
        lse_comb(m, s, sm_[2], ss_[2]);
        lse_comb(m, s, sm_[3], ss_[3]);
        int lbl = labels[row + 1];
        if (lbl < 0) lbl = 0;
        if (lbl >= VV) lbl = VV - 1;
        g_nll[r] = m + __logf(s) - C[(size_t)row * VV + lbl];
    }
}

__global__ void __launch_bounds__(256)
loss_reduce_kernel(float* __restrict__ out_loss)
{
    __shared__ float sh[256];
    float v = 0.f;
    for (int i = threadIdx.x; i < BB * (TT - 1); i += 256) v += g_nll[i];
    sh[threadIdx.x] = v;
    __syncthreads();
    for (int st = 128; st; st >>= 1) {
        if (threadIdx.x < st) sh[threadIdx.x] += sh[threadIdx.x + st];
        __syncthreads();
    }
    if (threadIdx.x == 0) *out_loss = sh[0] / (float)(BB * (TT - 1));
}

// ---------------- launch ----------------
extern "C" void kernel_launch(void* const* d_in, const int* in_sizes, int n_in,
                              void* d_out, int out_size)
{
    const float* hidden = nullptr;
    const float* weight = nullptr;
    const int*   labels = nullptr;
    for (int i = 0; i < n_in; i++) {
        if      (in_sizes[i] == MTOT * HH) hidden = (const float*)d_in[i];
        else if (in_sizes[i] == VV * HH)   weight = (const float*)d_in[i];
        else if (in_sizes[i] == BB * TT)   labels = (const int*)d_in[i];
    }
    float* out = (float*)d_out;

    cudaFuncSetAttribute(gemm_f16_kernel,
                         cudaFuncAttributeMaxDynamicSharedMemorySize, SMEM_TOTAL);

    pack_A_kernel<<<(32 * 64 * 256) / 256, 256>>>(hidden);
    pack_W_kernel<<<(NT * 64 * 256) / 256, 256>>>(weight);

    dim3 grid(MTOT / TM, NT);          // (32, 393)
    gemm_f16_kernel<<<grid, NTHREADS, SMEM_TOTAL>>>(out);

    loss_partial_kernel<<<BB * (TT - 1), 128>>>(out, labels);
    loss_reduce_kernel<<<1, 256>>>(out + (size_t)out_size - 1);
}